// round 15
// baseline (speedup 1.0000x reference)
#include <cuda_runtime.h>
#include <math.h>

#define B_ 16
#define N_ 2304
#define D_ 1024
#define H_ 1344
#define W_ 1344
#define M_ 8
#define HV_ 48
#define PH_ 28
#define NRAYS 24
#define NSAMP 20

#define NCH2 18           // chunks for rgb pass
#define CH2 128           // tokens per chunk
#define SUBT 8            // tokens per subtile
#define NSUB 16           // subtiles per chunk
#define K5_BLOCKS (NCH2 * B_)          // 288

#define K3_TILE 512
#define K3B 304                        // tiles split 184x12 + 120x11 = 3528
#define SDP 516                        // padded row stride (floats)

// ---------------- scratch ----------------
__device__ unsigned char g_packed[H_ * W_];
__device__ int           g_psum7[7][M_ * N_];              // strip-slot partial patch sums
__device__ float         g_part3T[256][320];               // [val(2x128)][k3 block]
__device__ float         g_partial[NCH2 * M_ * B_ * D_];   // 9.4 MB
__device__ float         g_locmax[NCH2 * M_ * B_];
__device__ float         g_locsum[NCH2 * M_ * B_];

// 24 ray angles: cos/sin of pi*r/12 (float-rounded from double)
__device__ __constant__ float c_cos[NRAYS] = {
    1.0f, 0.9659258262890683f, 0.8660254037844387f, 0.7071067811865476f,
    0.5000000000000001f, 0.25881904510252096f, 6.123233995736766e-17f,
    -0.25881904510252063f, -0.4999999999999998f, -0.7071067811865475f,
    -0.8660254037844387f, -0.9659258262890683f, -1.0f, -0.9659258262890684f,
    -0.8660254037844388f, -0.7071067811865477f, -0.5000000000000004f,
    -0.2588190451025215f, -1.8369701987210297e-16f, 0.2588190451025203f,
    0.49999999999999933f, 0.7071067811865474f, 0.8660254037844384f,
    0.9659258262890681f };
__device__ __constant__ float c_sin[NRAYS] = {
    0.0f, 0.25881904510252074f, 0.49999999999999994f, 0.7071067811865475f,
    0.8660254037844386f, 0.9659258262890682f, 1.0f, 0.9659258262890683f,
    0.8660254037844387f, 0.7071067811865476f, 0.49999999999999994f,
    0.258819045102521f, 1.2246467991473532e-16f, -0.25881904510252035f,
    -0.4999999999999997f, -0.7071067811865475f, -0.8660254037844384f,
    -0.9659258262890681f, -1.0f, -0.9659258262890684f, -0.8660254037844388f,
    -0.7071067811865477f, -0.5000000000000004f, -0.2588190451025216f };

// ---------------- helpers ----------------
__device__ __forceinline__ float blockSum(float v, float* sm) {
    int lane = threadIdx.x & 31, w = threadIdx.x >> 5;
    int nw = blockDim.x >> 5;
#pragma unroll
    for (int o = 16; o; o >>= 1) v += __shfl_down_sync(0xffffffffu, v, o);
    if (lane == 0) sm[w] = v;
    __syncthreads();
    if (w == 0) {
        v = (lane < nw) ? sm[lane] : 0.f;
#pragma unroll
        for (int o = 16; o; o >>= 1) v += __shfl_down_sync(0xffffffffu, v, o);
        if (lane == 0) sm[0] = v;
    }
    __syncthreads();
    float r = sm[0];
    __syncthreads();
    return r;
}

#define MBARRIER_INIT(mbar, count) \
    asm volatile("mbarrier.init.shared.b64 [%0], %1;" :: "r"(mbar), "r"((unsigned)(count)) : "memory")
#define MBARRIER_EXPECT_TX(mbar, bytes) \
    asm volatile("mbarrier.arrive.expect_tx.shared.b64 _, [%0], %1;" :: "r"(mbar), "r"((unsigned)(bytes)) : "memory")
#define BULK_COPY(dst_smem, src_gmem, bytes, mbar) \
    asm volatile("cp.async.bulk.shared::cluster.global.mbarrier::complete_tx::bytes [%0], [%1], %2, [%3];" \
        :: "r"(dst_smem), "l"(src_gmem), "r"((unsigned)(bytes)), "r"(mbar) : "memory")

__device__ __forceinline__ void mbarWait(unsigned mbar, unsigned parity) {
    asm volatile(
        "{\n\t.reg .pred P1;\n\t"
        "WAIT_LOOP_%=:\n\t"
        "mbarrier.try_wait.parity.acquire.cta.shared::cta.b64 P1, [%0], %1, 0x989680;\n\t"
        "@P1 bra.uni WAIT_DONE_%=;\n\t"
        "bra.uni WAIT_LOOP_%=;\n\t"
        "WAIT_DONE_%=:\n\t}"
        :: "r"(mbar), "r"(parity) : "memory");
}

__device__ __forceinline__ unsigned f2tf32(float f) {
    unsigned u;
    asm("cvt.rna.tf32.f32 %0, %1;" : "=r"(u) : "f"(f));
    return u;
}

__device__ __forceinline__ void mma_tf32(float* c, unsigned a0, unsigned a1,
                                         unsigned a2, unsigned a3,
                                         unsigned b0, unsigned b1) {
    asm volatile(
        "mma.sync.aligned.m16n8k8.row.col.f32.tf32.tf32.f32 "
        "{%0,%1,%2,%3}, {%4,%5,%6,%7}, {%8,%9}, {%0,%1,%2,%3};"
        : "+f"(c[0]), "+f"(c[1]), "+f"(c[2]), "+f"(c[3])
        : "r"(a0), "r"(a1), "r"(a2), "r"(a3), "r"(b0), "r"(b1));
}

// ---------------- K2: bulk-copy staged mask bitpack + per-patch sums ----------------
// grid = 336 strips of 4 rows, 512 threads. Mask rows staged via cp.async.bulk
// (8 planes x 5376 B per row), double-buffered; pack/count computed from smem.
#define K2_SMEM (2 * 8 * 1344 * 4 + 4 * 336 * 4 + 16)   // 91,408 B

__global__ void __launch_bounds__(512) k2_mask(const int* __restrict__ masks) {
    extern __shared__ float smemf[];
    int* buf = (int*)smemf;                                  // [2][8][1344]
    unsigned* scount = (unsigned*)(buf + 2 * 8 * 1344);      // [4][336]
    unsigned mbase = (unsigned)__cvta_generic_to_shared(scount + 4 * 336);  // 2 x 8B

    int tid = threadIdx.x;
    int y0 = blockIdx.x * 4;

    if (tid == 0) {
        MBARRIER_INIT(mbase + 0, 1);
        MBARRIER_INIT(mbase + 8, 1);
    }
    __syncthreads();

    auto stage = [&](int r) {
        if (tid == 0) {
            int bsel = r & 1;
            unsigned mb = mbase + bsel * 8;
            MBARRIER_EXPECT_TX(mb, 8 * 5376);
            unsigned dst = (unsigned)__cvta_generic_to_shared(buf + bsel * 8 * 1344);
#pragma unroll
            for (int m = 0; m < M_; m++)
                BULK_COPY(dst + m * 5376,
                          masks + ((size_t)m * H_ + (y0 + r)) * W_, 5376, mb);
        }
    };

    stage(0);
    stage(1);

    for (int r = 0; r < 4; r++) {
        mbarWait(mbase + (r & 1) * 8, (unsigned)((r / 2) & 1));
        __syncthreads();

        const int* bb = buf + (r & 1) * 8 * 1344;
        if (tid < 336) {
            int g = tid;
            unsigned pack = 0, cnt = 0;
#pragma unroll
            for (int m = 0; m < M_; m++) {
                int4 v = *(const int4*)(bb + m * 1344 + g * 4);
                unsigned q0 = (v.x != 0), q1 = (v.y != 0), q2 = (v.z != 0), q3 = (v.w != 0);
                pack |= (q0 | (q1 << 8) | (q2 << 16) | (q3 << 24)) << m;
                cnt  |= (q0 + q1 + q2 + q3) << (4 * m);
            }
            scount[r * 336 + g] = cnt;
            ((unsigned*)g_packed)[(size_t)(y0 + r) * 336 + g] = pack;
        }
        __syncthreads();
        if (r + 2 < 4) stage(r + 2);
    }

    if (tid < M_ * HV_) {
        int m = tid / HV_, pcol = tid - m * HV_;
        unsigned sum = 0;
#pragma unroll
        for (int r = 0; r < 4; r++)
#pragma unroll
            for (int k = 0; k < 7; k++)
                sum += (scount[r * 336 + pcol * 7 + k] >> (4 * m)) & 0xFu;
        int py = y0 / PH_;
        int slot = (y0 % PH_) / 4;
        g_psum7[slot][m * N_ + py * HV_ + pcol] = (int)sum;
    }
}

// soft2d from patch sum (matches original k2b numerics)
__device__ __forceinline__ float softFromPs(int ps) {
    float cov = (float)ps * (1.f / 784.f);
    return 1.f / (1.f + expf(-50.f * (cov - 0.3f)));
}
__device__ __forceinline__ int psAt(int m, int p) {
    int ps = 0;
#pragma unroll
    for (int s = 0; s < 7; s++) ps += g_psum7[s][m * N_ + p];
    return ps;
}

// ---------------- k3 device part: tf32 MMA depth stats, bulk-copy 3-stage ring ----------------
__device__ void k3_body(const float* __restrict__ depth, int k3id, float* smem) {
    float* sdb[3] = {smem, smem + 16 * SDP, smem + 32 * SDP};
    unsigned char* smaskb = (unsigned char*)(smem + 48 * SDP);   // 3 x 512B
    float* sredk = smem;                                         // alias (used after compute)
    unsigned mbase = (unsigned)__cvta_generic_to_shared(smem + 48 * SDP + 384);  // 3 x 8B

    int t0 = k3id * 11 + min(k3id, 184);
    int nt = 11 + (k3id < 184 ? 1 : 0);

    int tid = threadIdx.x;
    int lane = tid & 31, w = tid >> 5;    // 16 warps
    int gid = lane >> 2;
    int tig = lane & 3;

    if (tid == 0) {
        MBARRIER_INIT(mbase + 0, 1);
        MBARRIER_INIT(mbase + 8, 1);
        MBARRIER_INIT(mbase + 16, 1);
    }
    __syncthreads();

    float c_d[4]  = {0.f, 0.f, 0.f, 0.f};
    float c_d2[4] = {0.f, 0.f, 0.f, 0.f};

    auto stage = [&](int tt) {
        if (tid == 0) {
            int buf = tt % 3;
            unsigned mb = mbase + buf * 8;
            MBARRIER_EXPECT_TX(mb, 16 * 2048 + 512);
            size_t px0 = (size_t)(t0 + tt) * K3_TILE;
            unsigned dstb = (unsigned)__cvta_generic_to_shared(sdb[buf]);
#pragma unroll
            for (int b = 0; b < 16; b++)
                BULK_COPY(dstb + b * (SDP * 4), depth + (size_t)b * (H_ * W_) + px0, 2048, mb);
            BULK_COPY((unsigned)__cvta_generic_to_shared(smaskb + buf * 512),
                      g_packed + px0, 512, mb);
        }
    };

    stage(0);
    if (nt > 1) stage(1);

    for (int t = 0; t < nt; t++) {
        mbarWait(mbase + (t % 3) * 8, (unsigned)((t / 3) & 1));
        __syncthreads();                 // all compute of t-1 done before re-staging its buffer
        if (t + 2 < nt) stage(t + 2);

        float* sdt = sdb[t % 3];
        unsigned char* smt = smaskb + (t % 3) * 512;
        int pbase = w * 32;
#pragma unroll
        for (int s = 0; s < 4; s++) {
            int px = pbase + s * 8;
            float a0 = sdt[gid * SDP + px + tig];
            float a1 = sdt[(gid + 8) * SDP + px + tig];
            float a2 = sdt[gid * SDP + px + 4 + tig];
            float a3 = sdt[(gid + 8) * SDP + px + 4 + tig];
            unsigned ua0 = f2tf32(a0), ua1 = f2tf32(a1), ua2 = f2tf32(a2), ua3 = f2tf32(a3);
            unsigned uq0 = f2tf32(a0 * a0), uq1 = f2tf32(a1 * a1);
            unsigned uq2 = f2tf32(a2 * a2), uq3 = f2tf32(a3 * a3);
            unsigned byt0 = smt[px + tig];
            unsigned byt1 = smt[px + 4 + tig];
            unsigned b0 = ((byt0 >> gid) & 1u) ? 0x3F800000u : 0u;
            unsigned b1 = ((byt1 >> gid) & 1u) ? 0x3F800000u : 0u;
            mma_tf32(c_d,  ua0, ua1, ua2, ua3, b0, b1);
            mma_tf32(c_d2, uq0, uq1, uq2, uq3, b0, b1);
        }
        __syncthreads();   // compute(t) done before buffer (t)%3 can be re-staged
    }

    int p00 = gid * 8 + 2 * tig;
    int p10 = (gid + 8) * 8 + 2 * tig;
    sredk[w * 256 + p00]           = c_d[0];
    sredk[w * 256 + p00 + 1]       = c_d[1];
    sredk[w * 256 + p10]           = c_d[2];
    sredk[w * 256 + p10 + 1]       = c_d[3];
    sredk[w * 256 + 128 + p00]     = c_d2[0];
    sredk[w * 256 + 128 + p00 + 1] = c_d2[1];
    sredk[w * 256 + 128 + p10]     = c_d2[2];
    sredk[w * 256 + 128 + p10 + 1] = c_d2[3];
    __syncthreads();
    if (tid < 256) {
        float s = 0.f;
#pragma unroll
        for (int ww = 0; ww < 16; ww++) s += sredk[ww * 256 + tid];
        g_part3T[tid][k3id] = s;
    }
}

// ---------------- k5 device part: fused scores + online softmax, bulk-copy ring ----------------
__device__ void k5_body(const float* __restrict__ tok, const float* __restrict__ gw,
                        int c, int b, float* smem) {
    float* s_gw     = smem;                            // 1024
    float* s_buf    = smem + 1024;                     // 3 x 8192
    float* s_lsoft  = smem + 1024 + 3 * 8192;          // 1024  [m][128]
    float* s_schalf = s_lsoft + 1024;                  // 16
    float* s_e      = s_schalf + 16;                   // [SUBT][8]
    float* s_scale  = s_e + SUBT * 8;                  // 8
    unsigned mbase = (unsigned)__cvta_generic_to_shared(s_scale + 8);  // 3 x 8B

    int tid = threadIdx.x;
    int lane = tid & 31, w = tid >> 5;
    const float* gtok = tok + ((size_t)b * N_ + (size_t)c * CH2) * D_;

    ((float2*)s_gw)[tid] = ((const float2*)gw)[tid];

    if (tid == 0) {
        MBARRIER_INIT(mbase + 0, 1);
        MBARRIER_INIT(mbase + 8, 1);
        MBARRIER_INIT(mbase + 16, 1);
    }
    __syncthreads();

    auto stage = [&](int tt) {
        if (tid == 0) {
            int buf = tt % 3;
            unsigned mb = mbase + buf * 8;
            MBARRIER_EXPECT_TX(mb, 32768);
            BULK_COPY((unsigned)__cvta_generic_to_shared(s_buf + buf * 8192),
                      gtok + (size_t)tt * SUBT * D_, 32768, mb);
        }
    };

    stage(0);
    stage(1);

    // compute logsoft slice for this chunk (overlaps with in-flight bulk copies)
    for (int i = tid; i < M_ * CH2; i += 512) {
        int m = i >> 7, j = i & 127;
        float soft = softFromPs(psAt(m, c * CH2 + j));
        s_lsoft[i] = logf(fmaxf(soft, 1e-8f));
    }

    float2 acc2[M_];
#pragma unroll
    for (int m = 0; m < M_; m++) acc2[m] = make_float2(0.f, 0.f);
    float rm = -3.0e38f, rs = 0.f;

    for (int t = 0; t < NSUB; t++) {
        mbarWait(mbase + (t % 3) * 8, (unsigned)((t / 3) & 1));
        __syncthreads();                       // reads of tile t-1 done before its buffer re-staged
        if (t + 2 < NSUB) stage(t + 2);

        float* buf = s_buf + (t % 3) * 8192;

        // dots: warp w owns half (w&1) of token (w>>1)
        {
            int tok_j = w >> 1, half = w & 1;
            const float4* tp = (const float4*)(buf + (size_t)tok_j * D_ + half * 512);
            const float4* gp = (const float4*)(s_gw + half * 512);
            float acc = 0.f;
#pragma unroll
            for (int it = 0; it < 4; it++) {
                float4 a = tp[lane + it * 32];
                float4 g = gp[lane + it * 32];
                acc += a.x * g.x + a.y * g.y + a.z * g.z + a.w * g.w;
            }
#pragma unroll
            for (int o = 16; o; o >>= 1) acc += __shfl_down_sync(0xffffffffu, acc, o);
            if (lane == 0) s_schalf[w] = acc;
        }
        __syncthreads();

        if (w < 8) {
            int m = w;
            float v = -3.0e38f;
            if (lane < SUBT)
                v = s_schalf[2 * lane] + s_schalf[2 * lane + 1]
                  + s_lsoft[m * CH2 + t * SUBT + lane];
            float mx = v;
#pragma unroll
            for (int o = 16; o; o >>= 1) mx = fmaxf(mx, __shfl_xor_sync(0xffffffffu, mx, o));
            float nm = fmaxf(rm, mx);
            float sc = expf(rm - nm);
            float e = (lane < SUBT) ? expf(v - nm) : 0.f;
            if (lane < SUBT) s_e[lane * 8 + m] = e;
            float se = e;
#pragma unroll
            for (int o = 16; o; o >>= 1) se += __shfl_xor_sync(0xffffffffu, se, o);
            rs = rs * sc + se;
            rm = nm;
            if (lane == 0) s_scale[m] = sc;
        }
        __syncthreads();

        // accumulate: thread owns d-pair [2*tid, 2*tid+1] (scalar FFMA, compiler-scheduled)
        {
#pragma unroll
            for (int m = 0; m < M_; m++) {
                float sc = s_scale[m];
                acc2[m].x *= sc; acc2[m].y *= sc;
            }
#pragma unroll
            for (int j = 0; j < SUBT; j++) {
                float2 tv = *(const float2*)(buf + (size_t)j * D_ + tid * 2);
                float4 e0 = *(const float4*)(s_e + j * 8);
                float4 e1 = *(const float4*)(s_e + j * 8 + 4);
                acc2[0].x = fmaf(e0.x, tv.x, acc2[0].x); acc2[0].y = fmaf(e0.x, tv.y, acc2[0].y);
                acc2[1].x = fmaf(e0.y, tv.x, acc2[1].x); acc2[1].y = fmaf(e0.y, tv.y, acc2[1].y);
                acc2[2].x = fmaf(e0.z, tv.x, acc2[2].x); acc2[2].y = fmaf(e0.z, tv.y, acc2[2].y);
                acc2[3].x = fmaf(e0.w, tv.x, acc2[3].x); acc2[3].y = fmaf(e0.w, tv.y, acc2[3].y);
                acc2[4].x = fmaf(e1.x, tv.x, acc2[4].x); acc2[4].y = fmaf(e1.x, tv.y, acc2[4].y);
                acc2[5].x = fmaf(e1.y, tv.x, acc2[5].x); acc2[5].y = fmaf(e1.y, tv.y, acc2[5].y);
                acc2[6].x = fmaf(e1.z, tv.x, acc2[6].x); acc2[6].y = fmaf(e1.z, tv.y, acc2[6].y);
                acc2[7].x = fmaf(e1.w, tv.x, acc2[7].x); acc2[7].y = fmaf(e1.w, tv.y, acc2[7].y);
            }
        }
        // no end barrier: next iteration's post-wait barrier orders everything
    }

#pragma unroll
    for (int m = 0; m < M_; m++)
        *(float2*)&g_partial[(((size_t)c * M_ + m) * B_ + b) * D_ + tid * 2] = acc2[m];
    if (w < 8 && lane == 0) {
        int idx = (c * M_ + w) * B_ + b;
        g_locmax[idx] = rm;
        g_locsum[idx] = rs;
    }
}

// ---------------- K35: merged dispatch (288 k5 + 304 k3, 2 exact waves) ----------------
__global__ void __launch_bounds__(512, 2) k35(const float* __restrict__ tok,
                                              const float* __restrict__ gw,
                                              const float* __restrict__ depth) {
    extern __shared__ float smem[];
    int bid = blockIdx.x;
    if (bid < 2 * K5_BLOCKS) {
        if ((bid & 1) == 0) {
            int id = bid >> 1;
            k5_body(tok, gw, id % NCH2, id / NCH2, smem);
        } else {
            k3_body(depth, bid >> 1, smem);
        }
    } else {
        k3_body(depth, K5_BLOCKS + (bid - 2 * K5_BLOCKS), smem);
    }
}

// ---------------- bilinear helpers ----------------
__device__ __forceinline__ float bilin_border(const float* img, float x, float y) {
    x = fminf(fmaxf(x, 0.f), (float)(W_ - 1));
    y = fminf(fmaxf(y, 0.f), (float)(H_ - 1));
    float x0f = floorf(x), y0f = floorf(y);
    float wx = x - x0f, wy = y - y0f;
    int x0 = (int)x0f, y0 = (int)y0f;
    int x1 = min(x0 + 1, W_ - 1), y1 = min(y0 + 1, H_ - 1);
    return img[y0 * W_ + x0] * (1.f - wx) * (1.f - wy)
         + img[y0 * W_ + x1] * wx * (1.f - wy)
         + img[y1 * W_ + x0] * (1.f - wx) * wy
         + img[y1 * W_ + x1] * wx * wy;
}

__device__ __forceinline__ float tap48s(const float* img, int yy, int xx, float w) {
    if (xx >= 0 && xx < HV_ && yy >= 0 && yy < HV_) return img[yy * HV_ + xx] * w;
    return 0.f;
}

__device__ __forceinline__ float bilin_zeros48s(const float* img, float x, float y) {
    float x0f = floorf(x), y0f = floorf(y);
    float wx = x - x0f, wy = y - y0f;
    int x0 = (int)x0f, y0 = (int)y0f;
    float v = tap48s(img, y0, x0, (1.f - wx) * (1.f - wy));
    v += tap48s(img, y0, x0 + 1, wx * (1.f - wy));
    v += tap48s(img, y0 + 1, x0, (1.f - wx) * wy);
    v += tap48s(img, y0 + 1, x0 + 1, wx * wy);
    return v;
}

// ---------------- K67: epilogue (128 dep blocks + 256 half-D rgb blocks) ----------------
__global__ void __launch_bounds__(512) k67(const float* __restrict__ depth,
                                           const float* __restrict__ dw,
                                           const float* __restrict__ db,
                                           const float* __restrict__ gamma,
                                           const float* __restrict__ beta,
                                           float* __restrict__ out) {
    int bid = blockIdx.x;
    int tid = threadIdx.x;  // 512
    if (bid >= 128) {
        // ---- rgb combine: 2 blocks per (m,b), each owns half of D ----
        int j = bid - 128;
        int mb = j >> 1;
        int half = j & 1;
        int m = mb / B_, b = mb % B_;
        __shared__ float s_scale[NCH2];
        __shared__ float s_invS;
        if (tid == 0) {
            float MX = -1e30f;
#pragma unroll
            for (int c = 0; c < NCH2; c++)
                MX = fmaxf(MX, g_locmax[(c * M_ + m) * B_ + b]);
            float S = 0.f;
#pragma unroll
            for (int c = 0; c < NCH2; c++) {
                float sc = expf(g_locmax[(c * M_ + m) * B_ + b] - MX);
                s_scale[c] = sc;
                S += sc * g_locsum[(c * M_ + m) * B_ + b];
            }
            s_invS = 1.f / S;
        }
        __syncthreads();
        int d = half * 512 + tid;
        float a = 0.f;
#pragma unroll
        for (int c = 0; c < NCH2; c++) {
            float sc = s_scale[c];
            float p = g_partial[(((size_t)c * M_ + m) * B_ + b) * D_ + d];
            a = fmaf(sc, p, a);
        }
        out[((size_t)m * B_ + b) * D_ + d] = a * s_invS;
        return;
    }

    // ---- dep: soft2d + scalars (recomputed) + rays + stats + GEMV + LN ----
    int b = bid & 15, m = bid >> 4;
    __shared__ float sm[32];
    __shared__ float s_soft[N_];            // 9.2 KB
    __shared__ float s_stats[28];
    __shared__ float s_ds[NRAYS * NSAMP];
    __shared__ float s_sw[NRAYS * NSAMP];

    float cacc = 0.f, ss = 0.f, sx = 0.f, sy = 0.f;
    for (int p = tid; p < N_; p += 512) {
        int ps = psAt(m, p);
        float soft = softFromPs(ps);
        s_soft[p] = soft;
        cacc += (float)ps;
        ss += soft;
        sx += soft * (float)(p % HV_);
        sy += soft * (float)(p / HV_);
    }
    cacc = blockSum(cacc, sm);
    ss   = blockSum(ss, sm);
    sx   = blockSum(sx, sm);
    sy   = blockSum(sy, sm);
    float count = cacc;
    float soft_sum = ss + 1e-8f;
    float cx = sx / (soft_sum * (float)HV_);
    float cy = sy / (soft_sum * (float)HV_);
    float cxp = cx * (float)(W_ - 1);
    float cyp = cy * (float)(H_ - 1);

    float a = 0.f, a2 = 0.f;
    if (tid < K3B) {
        a  = g_part3T[b * 8 + m][tid];
        a2 = g_part3T[128 + b * 8 + m][tid];
    }
    float sum_d  = blockSum(a, sm);
    float sum_d2 = blockSum(a2, sm);

    float mean_d = sum_d / fmaxf(count, 1.f);
    float var = (sum_d2 - count * mean_d * mean_d) / fmaxf(count - 1.f, 1.f);
    float std_d = (count > 1.f) ? sqrtf(fmaxf(var, 0.f)) : 0.f;

    if (tid < NRAYS * NSAMP) {
        int r = tid / NSAMP, s = tid % NSAMP;
        float ca = c_cos[r];
        float sa = c_sin[r];
        float tv = (float)(31.831578947368421 * (double)s);   // 1344*0.45/19
        float x = cxp + ca * tv;
        float y = cyp + sa * tv;
        const float* dm = depth + (size_t)b * H_ * W_;
        s_ds[tid] = bilin_border(dm, x, y);
        float xp = x / (float)(W_ - 1) * (float)(HV_ - 1);
        float yp = y / (float)(H_ - 1) * (float)(HV_ - 1);
        float sw = bilin_zeros48s(s_soft, xp, yp);
        s_sw[tid] = fmaxf(sw, 1e-6f);
    }
    __syncthreads();

    if (tid < NRAYS) {
        float ws = 0.f, pr = 0.f;
#pragma unroll
        for (int s = 0; s < NSAMP; s++) {
            ws += s_sw[tid * NSAMP + s];
            pr += s_ds[tid * NSAMP + s] * s_sw[tid * NSAMP + s];
        }
        float ok = (count > 0.f) ? 1.f : 0.f;
        s_stats[4 + tid] = (pr / ws) * ok;
    }
    if (tid == 0) {
        float ok = (count > 0.f) ? 1.f : 0.f;
        s_stats[0] = mean_d * ok;
        s_stats[1] = std_d * ok;
        s_stats[2] = cx * ok;
        s_stats[3] = cy * ok;
    }
    __syncthreads();

    float h0 = db[tid], h1 = db[tid + 512];
#pragma unroll
    for (int k = 0; k < 28; k++) {
        float st = s_stats[k];
        h0 = fmaf(st, dw[k * D_ + tid], h0);
        h1 = fmaf(st, dw[k * D_ + tid + 512], h1);
    }
    float mu = blockSum(h0 + h1, sm) * (1.f / (float)D_);
    float e0 = h0 - mu, e1 = h1 - mu;
    float v2 = blockSum(e0 * e0 + e1 * e1, sm) * (1.f / (float)D_);
    float inv = rsqrtf(v2 + 1e-5f);
    size_t off = (size_t)(M_ * B_ * D_) + ((size_t)m * B_ + b) * D_;
    out[off + tid]       = e0 * inv * gamma[tid] + beta[tid];
    out[off + tid + 512] = e1 * inv * gamma[tid + 512] + beta[tid + 512];
}

// ---------------- launch ----------------
// k5 smem: (1024 + 3*8192 + 1024 + 16 + 64 + 8 + 6) * 4 = 106,968 B
// k3 smem: (48*516 + 384 + 6) * 4 = 100,632 B
#define K35_SMEM 107008

extern "C" void kernel_launch(void* const* d_in, const int* in_sizes, int n_in,
                              void* d_out, int out_size) {
    const float* tok   = (const float*)d_in[0];
    const float* depth = (const float*)d_in[1];
    const int*   masks = (const int*)d_in[2];
    const float* gw    = (const float*)d_in[3];
    const float* dw    = (const float*)d_in[4];
    const float* db    = (const float*)d_in[5];
    const float* gamma = (const float*)d_in[6];
    const float* beta  = (const float*)d_in[7];
    float* out = (float*)d_out;

    cudaFuncSetAttribute(k35, cudaFuncAttributeMaxDynamicSharedMemorySize, K35_SMEM);
    cudaFuncSetAttribute(k2_mask, cudaFuncAttributeMaxDynamicSharedMemorySize, K2_SMEM);

    k2_mask<<<336, 512, K2_SMEM>>>(masks);
    k35<<<K5_BLOCKS + K3B, 512, K35_SMEM>>>(tok, gw, depth);
    k67<<<128 + 256, 512>>>(depth, dw, db, gamma, beta, out);
}

// round 16
// speedup vs baseline: 1.0702x; 1.0702x over previous
#include <cuda_runtime.h>
#include <math.h>

#define B_ 16
#define N_ 2304
#define D_ 1024
#define H_ 1344
#define W_ 1344
#define M_ 8
#define HV_ 48
#define PH_ 28
#define NRAYS 24
#define NSAMP 20

#define NCH2 18           // chunks for rgb pass
#define CH2 128           // tokens per chunk
#define SUBT 8            // tokens per subtile
#define NSUB 16           // subtiles per chunk
#define K5_BLOCKS (NCH2 * B_)          // 288

#define K3_TILE 512
#define K3B 304                        // tiles split 184x12 + 120x11 = 3528
#define SDP 516                        // padded row stride (floats)

// ---------------- scratch ----------------
__device__ unsigned char g_packed[H_ * W_];
__device__ int           g_psum7[7][M_ * N_];              // strip-slot partial patch sums
__device__ float         g_part3T[256][320];               // [val(2x128)][k3 block]
__device__ float         g_partial[NCH2 * M_ * B_ * D_];   // 9.4 MB
__device__ float         g_locmax[NCH2 * M_ * B_];
__device__ float         g_locsum[NCH2 * M_ * B_];

// 24 ray angles: cos/sin of pi*r/12 (float-rounded from double)
__device__ __constant__ float c_cos[NRAYS] = {
    1.0f, 0.9659258262890683f, 0.8660254037844387f, 0.7071067811865476f,
    0.5000000000000001f, 0.25881904510252096f, 6.123233995736766e-17f,
    -0.25881904510252063f, -0.4999999999999998f, -0.7071067811865475f,
    -0.8660254037844387f, -0.9659258262890683f, -1.0f, -0.9659258262890684f,
    -0.8660254037844388f, -0.7071067811865477f, -0.5000000000000004f,
    -0.2588190451025215f, -1.8369701987210297e-16f, 0.2588190451025203f,
    0.49999999999999933f, 0.7071067811865474f, 0.8660254037844384f,
    0.9659258262890681f };
__device__ __constant__ float c_sin[NRAYS] = {
    0.0f, 0.25881904510252074f, 0.49999999999999994f, 0.7071067811865475f,
    0.8660254037844386f, 0.9659258262890682f, 1.0f, 0.9659258262890683f,
    0.8660254037844387f, 0.7071067811865476f, 0.49999999999999994f,
    0.258819045102521f, 1.2246467991473532e-16f, -0.25881904510252035f,
    -0.4999999999999997f, -0.7071067811865475f, -0.8660254037844384f,
    -0.9659258262890681f, -1.0f, -0.9659258262890684f, -0.8660254037844388f,
    -0.7071067811865477f, -0.5000000000000004f, -0.2588190451025216f };

// ---------------- helpers ----------------
__device__ __forceinline__ float blockSum(float v, float* sm) {
    int lane = threadIdx.x & 31, w = threadIdx.x >> 5;
    int nw = blockDim.x >> 5;
#pragma unroll
    for (int o = 16; o; o >>= 1) v += __shfl_down_sync(0xffffffffu, v, o);
    if (lane == 0) sm[w] = v;
    __syncthreads();
    if (w == 0) {
        v = (lane < nw) ? sm[lane] : 0.f;
#pragma unroll
        for (int o = 16; o; o >>= 1) v += __shfl_down_sync(0xffffffffu, v, o);
        if (lane == 0) sm[0] = v;
    }
    __syncthreads();
    float r = sm[0];
    __syncthreads();
    return r;
}

#define MBARRIER_INIT(mbar, count) \
    asm volatile("mbarrier.init.shared.b64 [%0], %1;" :: "r"(mbar), "r"((unsigned)(count)) : "memory")
#define MBARRIER_EXPECT_TX(mbar, bytes) \
    asm volatile("mbarrier.arrive.expect_tx.shared.b64 _, [%0], %1;" :: "r"(mbar), "r"((unsigned)(bytes)) : "memory")
#define BULK_COPY(dst_smem, src_gmem, bytes, mbar) \
    asm volatile("cp.async.bulk.shared::cluster.global.mbarrier::complete_tx::bytes [%0], [%1], %2, [%3];" \
        :: "r"(dst_smem), "l"(src_gmem), "r"((unsigned)(bytes)), "r"(mbar) : "memory")

__device__ __forceinline__ void mbarWait(unsigned mbar, unsigned parity) {
    asm volatile(
        "{\n\t.reg .pred P1;\n\t"
        "WAIT_LOOP_%=:\n\t"
        "mbarrier.try_wait.parity.acquire.cta.shared::cta.b64 P1, [%0], %1, 0x989680;\n\t"
        "@P1 bra.uni WAIT_DONE_%=;\n\t"
        "bra.uni WAIT_LOOP_%=;\n\t"
        "WAIT_DONE_%=:\n\t}"
        :: "r"(mbar), "r"(parity) : "memory");
}

__device__ __forceinline__ unsigned f2tf32(float f) {
    unsigned u;
    asm("cvt.rna.tf32.f32 %0, %1;" : "=r"(u) : "f"(f));
    return u;
}

__device__ __forceinline__ void mma_tf32(float* c, unsigned a0, unsigned a1,
                                         unsigned a2, unsigned a3,
                                         unsigned b0, unsigned b1) {
    asm volatile(
        "mma.sync.aligned.m16n8k8.row.col.f32.tf32.tf32.f32 "
        "{%0,%1,%2,%3}, {%4,%5,%6,%7}, {%8,%9}, {%0,%1,%2,%3};"
        : "+f"(c[0]), "+f"(c[1]), "+f"(c[2]), "+f"(c[3])
        : "r"(a0), "r"(a1), "r"(a2), "r"(a3), "r"(b0), "r"(b1));
}

// ---------------- K2: strip-streaming mask bitpack + per-patch sums (exact R14) ----------------
__global__ void __launch_bounds__(1024) k2_mask(const int* __restrict__ masks) {
    __shared__ unsigned spack[4 * 336];
    __shared__ unsigned scount[4 * 336];
    int tid = threadIdx.x;
    int y0 = blockIdx.x * 4;

    for (int i = tid; i < 4 * 336; i += 1024) {
        int r = i / 336, g = i - r * 336;
        const int* base = masks + ((size_t)(y0 + r)) * W_ + g * 4;
        unsigned pack = 0, cnt = 0;
#pragma unroll
        for (int m = 0; m < M_; m++) {
            int4 v = *(const int4*)(base + (size_t)m * (H_ * W_));
            unsigned q0 = (v.x != 0), q1 = (v.y != 0), q2 = (v.z != 0), q3 = (v.w != 0);
            pack |= (q0 | (q1 << 8) | (q2 << 16) | (q3 << 24)) << m;
            cnt  |= (q0 + q1 + q2 + q3) << (4 * m);
        }
        spack[i] = pack;
        scount[i] = cnt;
        ((unsigned*)g_packed)[(size_t)(y0 + r) * 336 + g] = pack;
    }
    __syncthreads();

    if (tid < M_ * HV_) {
        int m = tid / HV_, pcol = tid - m * HV_;
        unsigned sum = 0;
#pragma unroll
        for (int r = 0; r < 4; r++)
#pragma unroll
            for (int k = 0; k < 7; k++)
                sum += (scount[r * 336 + pcol * 7 + k] >> (4 * m)) & 0xFu;
        int py = y0 / PH_;
        int slot = (y0 % PH_) / 4;
        g_psum7[slot][m * N_ + py * HV_ + pcol] = (int)sum;
    }
}

// soft2d from patch sum (matches original k2b numerics)
__device__ __forceinline__ float softFromPs(int ps) {
    float cov = (float)ps * (1.f / 784.f);
    return 1.f / (1.f + expf(-50.f * (cov - 0.3f)));
}
__device__ __forceinline__ int psAt(int m, int p) {
    int ps = 0;
#pragma unroll
    for (int s = 0; s < 7; s++) ps += g_psum7[s][m * N_ + p];
    return ps;
}

// ---------------- k3 device part: tf32 MMA depth stats, bulk-copy 3-stage ring ----------------
__device__ void k3_body(const float* __restrict__ depth, int k3id, float* smem) {
    float* sdb[3] = {smem, smem + 16 * SDP, smem + 32 * SDP};
    unsigned char* smaskb = (unsigned char*)(smem + 48 * SDP);   // 3 x 512B
    float* sredk = smem;                                         // alias (used after compute)
    unsigned mbase = (unsigned)__cvta_generic_to_shared(smem + 48 * SDP + 384);  // 3 x 8B

    int t0 = k3id * 11 + min(k3id, 184);
    int nt = 11 + (k3id < 184 ? 1 : 0);

    int tid = threadIdx.x;
    int lane = tid & 31, w = tid >> 5;    // 16 warps
    int gid = lane >> 2;
    int tig = lane & 3;

    if (tid == 0) {
        MBARRIER_INIT(mbase + 0, 1);
        MBARRIER_INIT(mbase + 8, 1);
        MBARRIER_INIT(mbase + 16, 1);
    }
    __syncthreads();

    float c_d[4]  = {0.f, 0.f, 0.f, 0.f};
    float c_d2[4] = {0.f, 0.f, 0.f, 0.f};

    auto stage = [&](int tt) {
        if (tid == 0) {
            int buf = tt % 3;
            unsigned mb = mbase + buf * 8;
            MBARRIER_EXPECT_TX(mb, 16 * 2048 + 512);
            size_t px0 = (size_t)(t0 + tt) * K3_TILE;
            unsigned dstb = (unsigned)__cvta_generic_to_shared(sdb[buf]);
#pragma unroll
            for (int b = 0; b < 16; b++)
                BULK_COPY(dstb + b * (SDP * 4), depth + (size_t)b * (H_ * W_) + px0, 2048, mb);
            BULK_COPY((unsigned)__cvta_generic_to_shared(smaskb + buf * 512),
                      g_packed + px0, 512, mb);
        }
    };

    stage(0);
    if (nt > 1) stage(1);

    for (int t = 0; t < nt; t++) {
        mbarWait(mbase + (t % 3) * 8, (unsigned)((t / 3) & 1));
        __syncthreads();                 // all compute of t-1 done before re-staging its buffer
        if (t + 2 < nt) stage(t + 2);

        float* sdt = sdb[t % 3];
        unsigned char* smt = smaskb + (t % 3) * 512;
        int pbase = w * 32;
#pragma unroll
        for (int s = 0; s < 4; s++) {
            int px = pbase + s * 8;
            float a0 = sdt[gid * SDP + px + tig];
            float a1 = sdt[(gid + 8) * SDP + px + tig];
            float a2 = sdt[gid * SDP + px + 4 + tig];
            float a3 = sdt[(gid + 8) * SDP + px + 4 + tig];
            unsigned ua0 = f2tf32(a0), ua1 = f2tf32(a1), ua2 = f2tf32(a2), ua3 = f2tf32(a3);
            unsigned uq0 = f2tf32(a0 * a0), uq1 = f2tf32(a1 * a1);
            unsigned uq2 = f2tf32(a2 * a2), uq3 = f2tf32(a3 * a3);
            unsigned byt0 = smt[px + tig];
            unsigned byt1 = smt[px + 4 + tig];
            unsigned b0 = ((byt0 >> gid) & 1u) ? 0x3F800000u : 0u;
            unsigned b1 = ((byt1 >> gid) & 1u) ? 0x3F800000u : 0u;
            mma_tf32(c_d,  ua0, ua1, ua2, ua3, b0, b1);
            mma_tf32(c_d2, uq0, uq1, uq2, uq3, b0, b1);
        }
        __syncthreads();   // compute(t) done before buffer (t)%3 can be re-staged
    }

    int p00 = gid * 8 + 2 * tig;
    int p10 = (gid + 8) * 8 + 2 * tig;
    sredk[w * 256 + p00]           = c_d[0];
    sredk[w * 256 + p00 + 1]       = c_d[1];
    sredk[w * 256 + p10]           = c_d[2];
    sredk[w * 256 + p10 + 1]       = c_d[3];
    sredk[w * 256 + 128 + p00]     = c_d2[0];
    sredk[w * 256 + 128 + p00 + 1] = c_d2[1];
    sredk[w * 256 + 128 + p10]     = c_d2[2];
    sredk[w * 256 + 128 + p10 + 1] = c_d2[3];
    __syncthreads();
    if (tid < 256) {
        float s = 0.f;
#pragma unroll
        for (int ww = 0; ww < 16; ww++) s += sredk[ww * 256 + tid];
        g_part3T[tid][k3id] = s;
    }
}

// ---------------- k5 device part: fused scores + online softmax, bulk-copy ring ----------------
__device__ void k5_body(const float* __restrict__ tok, const float* __restrict__ gw,
                        int c, int b, float* smem) {
    float* s_buf    = smem;                            // 3 x 8192
    float* s_lsoft  = smem + 3 * 8192;                 // 1024  [m][128]
    float* s_schalf = s_lsoft + 1024;                  // 16
    float* s_e      = s_schalf + 16;                   // [SUBT][8]
    float* s_scale  = s_e + SUBT * 8;                  // 8
    unsigned mbase = (unsigned)__cvta_generic_to_shared(s_scale + 8);  // 3 x 8B

    int tid = threadIdx.x;
    int lane = tid & 31, w = tid >> 5;
    const float* gtok = tok + ((size_t)b * N_ + (size_t)c * CH2) * D_;

    if (tid == 0) {
        MBARRIER_INIT(mbase + 0, 1);
        MBARRIER_INIT(mbase + 8, 1);
        MBARRIER_INIT(mbase + 16, 1);
    }
    __syncthreads();

    auto stage = [&](int tt) {
        if (tid == 0) {
            int buf = tt % 3;
            unsigned mb = mbase + buf * 8;
            MBARRIER_EXPECT_TX(mb, 32768);
            BULK_COPY((unsigned)__cvta_generic_to_shared(s_buf + buf * 8192),
                      gtok + (size_t)tt * SUBT * D_, 32768, mb);
        }
    };

    stage(0);
    stage(1);

    // gate-weight fragment in registers: this thread's dot-phase addresses are
    // gw[half*512 + (lane + it*32)*4 ..] with half = w&1, fixed for all tiles.
    float4 rgw[4];
    {
        int half = w & 1;
        const float4* gp = (const float4*)(gw + half * 512);
#pragma unroll
        for (int it = 0; it < 4; it++) rgw[it] = gp[lane + it * 32];
    }

    // compute logsoft slice for this chunk (overlaps with in-flight bulk copies)
    for (int i = tid; i < M_ * CH2; i += 512) {
        int m = i >> 7, j = i & 127;
        float soft = softFromPs(psAt(m, c * CH2 + j));
        s_lsoft[i] = logf(fmaxf(soft, 1e-8f));
    }

    float2 acc2[M_];
#pragma unroll
    for (int m = 0; m < M_; m++) acc2[m] = make_float2(0.f, 0.f);
    float rm = -3.0e38f, rs = 0.f;

    for (int t = 0; t < NSUB; t++) {
        mbarWait(mbase + (t % 3) * 8, (unsigned)((t / 3) & 1));
        __syncthreads();                       // reads of tile t-1 done before its buffer re-staged
        if (t + 2 < NSUB) stage(t + 2);

        float* buf = s_buf + (t % 3) * 8192;

        // dots: warp w owns half (w&1) of token (w>>1); gw fragment in registers
        {
            int tok_j = w >> 1, half = w & 1;
            const float4* tp = (const float4*)(buf + (size_t)tok_j * D_ + half * 512);
            float acc = 0.f;
#pragma unroll
            for (int it = 0; it < 4; it++) {
                float4 a = tp[lane + it * 32];
                float4 g = rgw[it];
                acc += a.x * g.x + a.y * g.y + a.z * g.z + a.w * g.w;
            }
#pragma unroll
            for (int o = 16; o; o >>= 1) acc += __shfl_down_sync(0xffffffffu, acc, o);
            if (lane == 0) s_schalf[w] = acc;
        }
        __syncthreads();

        if (w < 8) {
            int m = w;
            float v = -3.0e38f;
            if (lane < SUBT)
                v = s_schalf[2 * lane] + s_schalf[2 * lane + 1]
                  + s_lsoft[m * CH2 + t * SUBT + lane];
            float mx = v;
#pragma unroll
            for (int o = 16; o; o >>= 1) mx = fmaxf(mx, __shfl_xor_sync(0xffffffffu, mx, o));
            float nm = fmaxf(rm, mx);
            float sc = expf(rm - nm);
            float e = (lane < SUBT) ? expf(v - nm) : 0.f;
            if (lane < SUBT) s_e[lane * 8 + m] = e;
            float se = e;
#pragma unroll
            for (int o = 16; o; o >>= 1) se += __shfl_xor_sync(0xffffffffu, se, o);
            rs = rs * sc + se;
            rm = nm;
            if (lane == 0) s_scale[m] = sc;
        }
        __syncthreads();

        // accumulate: thread owns d-pair [2*tid, 2*tid+1] (scalar FFMA, compiler-scheduled)
        {
#pragma unroll
            for (int m = 0; m < M_; m++) {
                float sc = s_scale[m];
                acc2[m].x *= sc; acc2[m].y *= sc;
            }
#pragma unroll
            for (int j = 0; j < SUBT; j++) {
                float2 tv = *(const float2*)(buf + (size_t)j * D_ + tid * 2);
                float4 e0 = *(const float4*)(s_e + j * 8);
                float4 e1 = *(const float4*)(s_e + j * 8 + 4);
                acc2[0].x = fmaf(e0.x, tv.x, acc2[0].x); acc2[0].y = fmaf(e0.x, tv.y, acc2[0].y);
                acc2[1].x = fmaf(e0.y, tv.x, acc2[1].x); acc2[1].y = fmaf(e0.y, tv.y, acc2[1].y);
                acc2[2].x = fmaf(e0.z, tv.x, acc2[2].x); acc2[2].y = fmaf(e0.z, tv.y, acc2[2].y);
                acc2[3].x = fmaf(e0.w, tv.x, acc2[3].x); acc2[3].y = fmaf(e0.w, tv.y, acc2[3].y);
                acc2[4].x = fmaf(e1.x, tv.x, acc2[4].x); acc2[4].y = fmaf(e1.x, tv.y, acc2[4].y);
                acc2[5].x = fmaf(e1.y, tv.x, acc2[5].x); acc2[5].y = fmaf(e1.y, tv.y, acc2[5].y);
                acc2[6].x = fmaf(e1.z, tv.x, acc2[6].x); acc2[6].y = fmaf(e1.z, tv.y, acc2[6].y);
                acc2[7].x = fmaf(e1.w, tv.x, acc2[7].x); acc2[7].y = fmaf(e1.w, tv.y, acc2[7].y);
            }
        }
        // no end barrier: next iteration's post-wait barrier orders everything
    }

#pragma unroll
    for (int m = 0; m < M_; m++)
        *(float2*)&g_partial[(((size_t)c * M_ + m) * B_ + b) * D_ + tid * 2] = acc2[m];
    if (w < 8 && lane == 0) {
        int idx = (c * M_ + w) * B_ + b;
        g_locmax[idx] = rm;
        g_locsum[idx] = rs;
    }
}

// ---------------- K35: merged dispatch (288 k5 + 304 k3, 2 exact waves) ----------------
__global__ void __launch_bounds__(512, 2) k35(const float* __restrict__ tok,
                                              const float* __restrict__ gw,
                                              const float* __restrict__ depth) {
    extern __shared__ float smem[];
    int bid = blockIdx.x;
    if (bid < 2 * K5_BLOCKS) {
        if ((bid & 1) == 0) {
            int id = bid >> 1;
            k5_body(tok, gw, id % NCH2, id / NCH2, smem);
        } else {
            k3_body(depth, bid >> 1, smem);
        }
    } else {
        k3_body(depth, K5_BLOCKS + (bid - 2 * K5_BLOCKS), smem);
    }
}

// ---------------- bilinear helpers ----------------
__device__ __forceinline__ float bilin_border(const float* img, float x, float y) {
    x = fminf(fmaxf(x, 0.f), (float)(W_ - 1));
    y = fminf(fmaxf(y, 0.f), (float)(H_ - 1));
    float x0f = floorf(x), y0f = floorf(y);
    float wx = x - x0f, wy = y - y0f;
    int x0 = (int)x0f, y0 = (int)y0f;
    int x1 = min(x0 + 1, W_ - 1), y1 = min(y0 + 1, H_ - 1);
    return img[y0 * W_ + x0] * (1.f - wx) * (1.f - wy)
         + img[y0 * W_ + x1] * wx * (1.f - wy)
         + img[y1 * W_ + x0] * (1.f - wx) * wy
         + img[y1 * W_ + x1] * wx * wy;
}

__device__ __forceinline__ float tap48s(const float* img, int yy, int xx, float w) {
    if (xx >= 0 && xx < HV_ && yy >= 0 && yy < HV_) return img[yy * HV_ + xx] * w;
    return 0.f;
}

__device__ __forceinline__ float bilin_zeros48s(const float* img, float x, float y) {
    float x0f = floorf(x), y0f = floorf(y);
    float wx = x - x0f, wy = y - y0f;
    int x0 = (int)x0f, y0 = (int)y0f;
    float v = tap48s(img, y0, x0, (1.f - wx) * (1.f - wy));
    v += tap48s(img, y0, x0 + 1, wx * (1.f - wy));
    v += tap48s(img, y0 + 1, x0, (1.f - wx) * wy);
    v += tap48s(img, y0 + 1, x0 + 1, wx * wy);
    return v;
}

// ---------------- K67: epilogue (128 dep blocks + 256 half-D rgb blocks) ----------------
__global__ void __launch_bounds__(512) k67(const float* __restrict__ depth,
                                           const float* __restrict__ dw,
                                           const float* __restrict__ db,
                                           const float* __restrict__ gamma,
                                           const float* __restrict__ beta,
                                           float* __restrict__ out) {
    int bid = blockIdx.x;
    int tid = threadIdx.x;  // 512
    if (bid >= 128) {
        // ---- rgb combine: 2 blocks per (m,b), each owns half of D ----
        int j = bid - 128;
        int mb = j >> 1;
        int half = j & 1;
        int m = mb / B_, b = mb % B_;
        __shared__ float s_scale[NCH2];
        __shared__ float s_invS;
        if (tid == 0) {
            float MX = -1e30f;
#pragma unroll
            for (int c = 0; c < NCH2; c++)
                MX = fmaxf(MX, g_locmax[(c * M_ + m) * B_ + b]);
            float S = 0.f;
#pragma unroll
            for (int c = 0; c < NCH2; c++) {
                float sc = expf(g_locmax[(c * M_ + m) * B_ + b] - MX);
                s_scale[c] = sc;
                S += sc * g_locsum[(c * M_ + m) * B_ + b];
            }
            s_invS = 1.f / S;
        }
        __syncthreads();
        int d = half * 512 + tid;
        float a = 0.f;
#pragma unroll
        for (int c = 0; c < NCH2; c++) {
            float sc = s_scale[c];
            float p = g_partial[(((size_t)c * M_ + m) * B_ + b) * D_ + d];
            a = fmaf(sc, p, a);
        }
        out[((size_t)m * B_ + b) * D_ + d] = a * s_invS;
        return;
    }

    // ---- dep: soft2d + scalars (recomputed) + rays + stats + GEMV + LN ----
    int b = bid & 15, m = bid >> 4;
    __shared__ float sm[32];
    __shared__ float s_soft[N_];            // 9.2 KB
    __shared__ float s_stats[28];
    __shared__ float s_ds[NRAYS * NSAMP];
    __shared__ float s_sw[NRAYS * NSAMP];

    float cacc = 0.f, ss = 0.f, sx = 0.f, sy = 0.f;
    for (int p = tid; p < N_; p += 512) {
        int ps = psAt(m, p);
        float soft = softFromPs(ps);
        s_soft[p] = soft;
        cacc += (float)ps;
        ss += soft;
        sx += soft * (float)(p % HV_);
        sy += soft * (float)(p / HV_);
    }
    cacc = blockSum(cacc, sm);
    ss   = blockSum(ss, sm);
    sx   = blockSum(sx, sm);
    sy   = blockSum(sy, sm);
    float count = cacc;
    float soft_sum = ss + 1e-8f;
    float cx = sx / (soft_sum * (float)HV_);
    float cy = sy / (soft_sum * (float)HV_);
    float cxp = cx * (float)(W_ - 1);
    float cyp = cy * (float)(H_ - 1);

    float a = 0.f, a2 = 0.f;
    if (tid < K3B) {
        a  = g_part3T[b * 8 + m][tid];
        a2 = g_part3T[128 + b * 8 + m][tid];
    }
    float sum_d  = blockSum(a, sm);
    float sum_d2 = blockSum(a2, sm);

    float mean_d = sum_d / fmaxf(count, 1.f);
    float var = (sum_d2 - count * mean_d * mean_d) / fmaxf(count - 1.f, 1.f);
    float std_d = (count > 1.f) ? sqrtf(fmaxf(var, 0.f)) : 0.f;

    if (tid < NRAYS * NSAMP) {
        int r = tid / NSAMP, s = tid % NSAMP;
        float ca = c_cos[r];
        float sa = c_sin[r];
        float tv = (float)(31.831578947368421 * (double)s);   // 1344*0.45/19
        float x = cxp + ca * tv;
        float y = cyp + sa * tv;
        const float* dm = depth + (size_t)b * H_ * W_;
        s_ds[tid] = bilin_border(dm, x, y);
        float xp = x / (float)(W_ - 1) * (float)(HV_ - 1);
        float yp = y / (float)(H_ - 1) * (float)(HV_ - 1);
        float sw = bilin_zeros48s(s_soft, xp, yp);
        s_sw[tid] = fmaxf(sw, 1e-6f);
    }
    __syncthreads();

    if (tid < NRAYS) {
        float ws = 0.f, pr = 0.f;
#pragma unroll
        for (int s = 0; s < NSAMP; s++) {
            ws += s_sw[tid * NSAMP + s];
            pr += s_ds[tid * NSAMP + s] * s_sw[tid * NSAMP + s];
        }
        float ok = (count > 0.f) ? 1.f : 0.f;
        s_stats[4 + tid] = (pr / ws) * ok;
    }
    if (tid == 0) {
        float ok = (count > 0.f) ? 1.f : 0.f;
        s_stats[0] = mean_d * ok;
        s_stats[1] = std_d * ok;
        s_stats[2] = cx * ok;
        s_stats[3] = cy * ok;
    }
    __syncthreads();

    float h0 = db[tid], h1 = db[tid + 512];
#pragma unroll
    for (int k = 0; k < 28; k++) {
        float st = s_stats[k];
        h0 = fmaf(st, dw[k * D_ + tid], h0);
        h1 = fmaf(st, dw[k * D_ + tid + 512], h1);
    }
    float mu = blockSum(h0 + h1, sm) * (1.f / (float)D_);
    float e0 = h0 - mu, e1 = h1 - mu;
    float v2 = blockSum(e0 * e0 + e1 * e1, sm) * (1.f / (float)D_);
    float inv = rsqrtf(v2 + 1e-5f);
    size_t off = (size_t)(M_ * B_ * D_) + ((size_t)m * B_ + b) * D_;
    out[off + tid]       = e0 * inv * gamma[tid] + beta[tid];
    out[off + tid + 512] = e1 * inv * gamma[tid + 512] + beta[tid + 512];
}

// ---------------- launch ----------------
// k5 smem: (3*8192 + 1024 + 16 + 64 + 8 + 6) * 4 = 103,272 B
// k3 smem: (48*516 + 384 + 6) * 4 = 100,632 B
#define K35_SMEM 103296

extern "C" void kernel_launch(void* const* d_in, const int* in_sizes, int n_in,
                              void* d_out, int out_size) {
    const float* tok   = (const float*)d_in[0];
    const float* depth = (const float*)d_in[1];
    const int*   masks = (const int*)d_in[2];
    const float* gw    = (const float*)d_in[3];
    const float* dw    = (const float*)d_in[4];
    const float* db    = (const float*)d_in[5];
    const float* gamma = (const float*)d_in[6];
    const float* beta  = (const float*)d_in[7];
    float* out = (float*)d_out;

    cudaFuncSetAttribute(k35, cudaFuncAttributeMaxDynamicSharedMemorySize, K35_SMEM);

    k2_mask<<<336, 1024>>>(masks);
    k35<<<K5_BLOCKS + K3B, 512, K35_SMEM>>>(tok, gw, depth);
    k67<<<128 + 256, 512>>>(depth, dw, db, gamma, beta, out);
}